// round 3
// baseline (speedup 1.0000x reference)
#include <cuda_runtime.h>
#include <cstdint>

#define Dd 512
#define Bb 32
#define Ss 2048

// gate_prob scratch (B*S fp32) — device global, no allocation
__device__ float g_gate[Bb * Ss];

__device__ __forceinline__ uint32_t f2tf(float x) {
    uint32_t r;
    asm("cvt.rna.tf32.f32 %0, %1;" : "=r"(r) : "f"(x));
    return r;
}

__device__ __forceinline__ void mma8(float* d, const uint32_t* a, uint32_t b0, uint32_t b1) {
    asm volatile(
        "mma.sync.aligned.m16n8k8.row.col.f32.tf32.tf32.f32 "
        "{%0,%1,%2,%3}, {%4,%5,%6,%7}, {%8,%9}, {%0,%1,%2,%3};\n"
        : "+f"(d[0]), "+f"(d[1]), "+f"(d[2]), "+f"(d[3])
        : "r"(a[0]), "r"(a[1]), "r"(a[2]), "r"(a[3]), "r"(b0), "r"(b1));
}

__device__ __forceinline__ void cpa16(float* dst, const float* src) {
    uint32_t s = (uint32_t)__cvta_generic_to_shared(dst);
    asm volatile("cp.async.cg.shared.global [%0], [%1], 16;\n" :: "r"(s), "l"(src));
}
#define CP_COMMIT() asm volatile("cp.async.commit_group;\n" ::: "memory")
#define CP_WAIT1()  asm volatile("cp.async.wait_group 1;\n" ::: "memory")
#define CP_WAIT0()  asm volatile("cp.async.wait_group 0;\n" ::: "memory")

// ============================================================================
// Kernel G: gate_prob[b,s] = sigmoid( (relu(old_x@W1^T + b1) + old_x) . W2 + b2 )
// CTA: 64 rows of one batch, old_x tile resident in SMEM (64x512 fp32),
// streams W1 in 128-col e-chunks x 32-wide K-tiles (cp.async double buffer).
// ============================================================================
#define GM 64
#define GN 128
#define GK 32
#define GASTR 516   // 512 + 4 pad -> bank-conflict-free frag loads
#define GBSTR 36    // 32 + 4 pad

__global__ void __launch_bounds__(256) gate_kernel(
    const float* __restrict__ oldx, const int* __restrict__ lang,
    const float* __restrict__ W1all, const float* __restrict__ b1all,
    const float* __restrict__ W2all, const float* __restrict__ b2all)
{
    extern __shared__ float sm[];
    float* As   = sm;                       // GM * GASTR
    float* Bsb  = sm + GM * GASTR;          // 2 stages * GN * GBSTR
    float* slog = Bsb + 2 * GN * GBSTR;     // GM

    const int mt = blockIdx.x, b = blockIdx.y;
    const int tid = threadIdx.x;
    const int lg = lang[b];
    const float* xb = oldx + ((size_t)b * Ss + (size_t)mt * GM) * Dd;
    const float* W1 = W1all + (size_t)lg * Dd * Dd;
    const float* b1 = b1all + (size_t)lg * Dd;
    const float* W2 = W2all + (size_t)lg * Dd;
    const float  b2v = b2all[lg];

    // resident A (old_x tile) 64x512
    #pragma unroll
    for (int t = 0; t < 32; t++) {
        int chunk = tid + t * 256;          // 0..8191 float4 chunks
        int row = chunk >> 7;               // 128 float4 per row
        int c4  = (chunk & 127) * 4;
        *(float4*)&As[row * GASTR + c4] = *(const float4*)(xb + row * Dd + c4);
    }
    if (tid < GM) slog[tid] = 0.f;
    __syncthreads();

    const int wid = tid >> 5, lane = tid & 31, g = lane >> 2, t4 = lane & 3;
    const int wm = (wid & 1) * 32, wn = (wid >> 1) * 32;   // 2m x 4n warps, tile 32x32

    float plog[4] = {0.f, 0.f, 0.f, 0.f};

    for (int ec = 0; ec < Dd / GN; ec++) {
        const float* Wt = W1 + (size_t)(ec * GN) * Dd;
        float acc[2][4][4];
        #pragma unroll
        for (int am = 0; am < 2; am++)
            #pragma unroll
            for (int an = 0; an < 4; an++)
                #pragma unroll
                for (int q = 0; q < 4; q++) acc[am][an][q] = 0.f;

        // prefetch stage 0
        #pragma unroll
        for (int t = 0; t < 4; t++) {
            int chunk = tid + t * 256;      // 0..1023 (128 rows * 8 float4)
            int row = chunk >> 3;
            int c4  = (chunk & 7) * 4;
            cpa16(&Bsb[row * GBSTR + c4], Wt + row * Dd + c4);
        }
        CP_COMMIT();

        for (int kc = 0; kc < Dd / GK; kc++) {
            int cur = kc & 1, nxt = cur ^ 1;
            if (kc < Dd / GK - 1) {
                int k0 = (kc + 1) * GK;
                #pragma unroll
                for (int t = 0; t < 4; t++) {
                    int chunk = tid + t * 256;
                    int row = chunk >> 3;
                    int c4  = (chunk & 7) * 4;
                    cpa16(&Bsb[nxt * GN * GBSTR + row * GBSTR + c4], Wt + row * Dd + k0 + c4);
                }
                CP_COMMIT();
                CP_WAIT1();
            } else {
                CP_WAIT0();
            }
            __syncthreads();
            const float* Bc = &Bsb[cur * GN * GBSTR];
            #pragma unroll
            for (int ks = 0; ks < 4; ks++) {
                int kg = kc * GK + ks * 8;
                uint32_t af[2][4];
                #pragma unroll
                for (int am = 0; am < 2; am++) {
                    int r0 = wm + am * 16 + g;
                    af[am][0] = f2tf(As[r0 * GASTR + kg + t4]);
                    af[am][1] = f2tf(As[(r0 + 8) * GASTR + kg + t4]);
                    af[am][2] = f2tf(As[r0 * GASTR + kg + t4 + 4]);
                    af[am][3] = f2tf(As[(r0 + 8) * GASTR + kg + t4 + 4]);
                }
                #pragma unroll
                for (int an = 0; an < 4; an++) {
                    int n = wn + an * 8 + g;
                    uint32_t bf0 = f2tf(Bc[n * GBSTR + ks * 8 + t4]);
                    uint32_t bf1 = f2tf(Bc[n * GBSTR + ks * 8 + t4 + 4]);
                    #pragma unroll
                    for (int am = 0; am < 2; am++)
                        mma8(acc[am][an], af[am], bf0, bf1);
                }
            }
            __syncthreads();
        }

        // chunk epilogue: relu + bias + old_x, dot with W2 -> per-row partial
        #pragma unroll
        for (int am = 0; am < 2; am++) {
            #pragma unroll
            for (int i = 0; i < 2; i++) {
                int r = wm + am * 16 + g + i * 8;
                float part = 0.f;
                #pragma unroll
                for (int an = 0; an < 4; an++) {
                    int e0 = ec * GN + wn + an * 8 + t4 * 2;
                    float c0 = acc[am][an][2 * i], c1 = acc[am][an][2 * i + 1];
                    float h0 = fmaxf(c0 + __ldg(&b1[e0]), 0.f) + As[r * GASTR + e0];
                    float h1 = fmaxf(c1 + __ldg(&b1[e0 + 1]), 0.f) + As[r * GASTR + e0 + 1];
                    part += h0 * __ldg(&W2[e0]) + h1 * __ldg(&W2[e0 + 1]);
                }
                plog[am * 2 + i] += part;
            }
        }
    }

    // reduce partials across the 4 lanes of each quad, then smem atomics
    #pragma unroll
    for (int q = 0; q < 4; q++) {
        plog[q] += __shfl_xor_sync(0xffffffffu, plog[q], 1);
        plog[q] += __shfl_xor_sync(0xffffffffu, plog[q], 2);
    }
    if (t4 == 0) {
        #pragma unroll
        for (int am = 0; am < 2; am++)
            #pragma unroll
            for (int i = 0; i < 2; i++)
                atomicAdd(&slog[wm + am * 16 + g + i * 8], plog[am * 2 + i]);
    }
    __syncthreads();
    if (tid < GM) {
        float logit = slog[tid] + b2v;
        g_gate[(size_t)b * Ss + (size_t)mt * GM + tid] = 1.f / (1.f + expf(-logit));
    }
}

// ============================================================================
// Kernel M: out = (1-p) * x@share_W^T + p * x@langs_W[lang]^T
// CTA: 128x64 output tile; one A (x) stream feeds TWO B operand streams.
// cp.async double-buffered, tf32 mma, fused combine epilogue.
// ============================================================================
#define MMt 128
#define MNt 64
#define MKt 32
#define MASTR 36
#define MBSTR 36

__global__ void __launch_bounds__(256) main_kernel(
    const float* __restrict__ x, const int* __restrict__ lang,
    const float* __restrict__ shareW, const float* __restrict__ langsW,
    float* __restrict__ out)
{
    extern __shared__ float sm[];
    float* As = sm;                           // 2 * MMt * MASTR
    float* Bs = sm + 2 * MMt * MASTR;         // 2 stages * 2 tensors * MNt * MBSTR

    const int nt = blockIdx.x, mt = blockIdx.y, b = blockIdx.z;
    const int tid = threadIdx.x;
    const int lg = lang[b];
    const float* xb = x + ((size_t)b * Ss + (size_t)mt * MMt) * Dd;
    const float* ws = shareW + (size_t)nt * MNt * Dd;
    const float* wl = langsW + (size_t)lg * Dd * Dd + (size_t)nt * MNt * Dd;

    float accS[2][4][4], accL[2][4][4];
    #pragma unroll
    for (int am = 0; am < 2; am++)
        #pragma unroll
        for (int an = 0; an < 4; an++)
            #pragma unroll
            for (int q = 0; q < 4; q++) { accS[am][an][q] = 0.f; accL[am][an][q] = 0.f; }

    const int wid = tid >> 5, lane = tid & 31, g = lane >> 2, t4 = lane & 3;
    const int wm = (wid & 3) * 32, wn = (wid >> 2) * 32;  // 4m x 2n warps, tile 32x32

    // prefetch stage 0
    {
        #pragma unroll
        for (int t = 0; t < 4; t++) {                 // A: 128 rows * 8 float4
            int chunk = tid + t * 256;
            int row = chunk >> 3;
            int c4  = (chunk & 7) * 4;
            cpa16(&As[row * MASTR + c4], xb + row * Dd + c4);
        }
        #pragma unroll
        for (int t = 0; t < 2; t++) {                 // B: 64 rows * 8 float4, x2 tensors
            int chunk = tid + t * 256;
            int row = chunk >> 3;
            int c4  = (chunk & 7) * 4;
            cpa16(&Bs[0 * MNt * MBSTR + row * MBSTR + c4], ws + row * Dd + c4);
            cpa16(&Bs[1 * MNt * MBSTR + row * MBSTR + c4], wl + row * Dd + c4);
        }
        CP_COMMIT();
    }

    for (int kc = 0; kc < Dd / MKt; kc++) {
        int cur = kc & 1, nxt = cur ^ 1;
        if (kc < Dd / MKt - 1) {
            int k0 = (kc + 1) * MKt;
            #pragma unroll
            for (int t = 0; t < 4; t++) {
                int chunk = tid + t * 256;
                int row = chunk >> 3;
                int c4  = (chunk & 7) * 4;
                cpa16(&As[nxt * MMt * MASTR + row * MASTR + c4], xb + row * Dd + k0 + c4);
            }
            #pragma unroll
            for (int t = 0; t < 2; t++) {
                int chunk = tid + t * 256;
                int row = chunk >> 3;
                int c4  = (chunk & 7) * 4;
                cpa16(&Bs[(nxt * 2 + 0) * MNt * MBSTR + row * MBSTR + c4], ws + row * Dd + k0 + c4);
                cpa16(&Bs[(nxt * 2 + 1) * MNt * MBSTR + row * MBSTR + c4], wl + row * Dd + k0 + c4);
            }
            CP_COMMIT();
            CP_WAIT1();
        } else {
            CP_WAIT0();
        }
        __syncthreads();
        const float* Ac  = &As[cur * MMt * MASTR];
        const float* Bcs = &Bs[(cur * 2 + 0) * MNt * MBSTR];
        const float* Bcl = &Bs[(cur * 2 + 1) * MNt * MBSTR];
        #pragma unroll
        for (int ks = 0; ks < 4; ks++) {
            int k0 = ks * 8;
            uint32_t af[2][4];
            #pragma unroll
            for (int am = 0; am < 2; am++) {
                int r0 = wm + am * 16 + g;
                af[am][0] = f2tf(Ac[r0 * MASTR + k0 + t4]);
                af[am][1] = f2tf(Ac[(r0 + 8) * MASTR + k0 + t4]);
                af[am][2] = f2tf(Ac[r0 * MASTR + k0 + t4 + 4]);
                af[am][3] = f2tf(Ac[(r0 + 8) * MASTR + k0 + t4 + 4]);
            }
            #pragma unroll
            for (int an = 0; an < 4; an++) {
                int n = wn + an * 8 + g;
                uint32_t bs0 = f2tf(Bcs[n * MBSTR + k0 + t4]);
                uint32_t bs1 = f2tf(Bcs[n * MBSTR + k0 + t4 + 4]);
                uint32_t bl0 = f2tf(Bcl[n * MBSTR + k0 + t4]);
                uint32_t bl1 = f2tf(Bcl[n * MBSTR + k0 + t4 + 4]);
                #pragma unroll
                for (int am = 0; am < 2; am++) {
                    mma8(accS[am][an], af[am], bs0, bs1);
                    mma8(accL[am][an], af[am], bl0, bl1);
                }
            }
        }
        __syncthreads();
    }

    // combine epilogue
    const size_t mbase = (size_t)b * Ss + (size_t)mt * MMt;
    #pragma unroll
    for (int am = 0; am < 2; am++) {
        #pragma unroll
        for (int i = 0; i < 2; i++) {
            int r = wm + am * 16 + g + i * 8;
            float p  = g_gate[mbase + r];
            float q_ = 1.f - p;
            float* op = out + (mbase + r) * Dd + nt * MNt + wn;
            #pragma unroll
            for (int an = 0; an < 4; an++) {
                float v0 = accS[am][an][2 * i]     * q_ + accL[am][an][2 * i]     * p;
                float v1 = accS[am][an][2 * i + 1] * q_ + accL[am][an][2 * i + 1] * p;
                float2 v = make_float2(v0, v1);
                *(float2*)(op + an * 8 + t4 * 2) = v;
            }
        }
    }
}

// ============================================================================
extern "C" void kernel_launch(void* const* d_in, const int* in_sizes, int n_in,
                              void* d_out, int out_size) {
    const float* oldx   = (const float*)d_in[0];
    const float* x      = (const float*)d_in[1];
    const int*   lang   = (const int*)d_in[2];
    const float* shareW = (const float*)d_in[3];
    const float* langsW = (const float*)d_in[4];
    const float* gW1    = (const float*)d_in[5];
    const float* gb1    = (const float*)d_in[6];
    const float* gW2    = (const float*)d_in[7];
    const float* gb2    = (const float*)d_in[8];
    float* out = (float*)d_out;

    const int gsmem = (GM * GASTR + 2 * GN * GBSTR + GM) * (int)sizeof(float);
    const int msmem = (2 * MMt * MASTR + 4 * MNt * MBSTR) * (int)sizeof(float);
    cudaFuncSetAttribute(gate_kernel, cudaFuncAttributeMaxDynamicSharedMemorySize, gsmem);
    cudaFuncSetAttribute(main_kernel, cudaFuncAttributeMaxDynamicSharedMemorySize, msmem);

    dim3 gg(Ss / GM, Bb);
    gate_kernel<<<gg, 256, gsmem>>>(oldx, lang, gW1, gb1, gW2, gb2);

    dim3 gm(Dd / MNt, Ss / MMt, Bb);
    main_kernel<<<gm, 256, msmem>>>(x, lang, shareW, langsW, out);
}

// round 10
// speedup vs baseline: 1.1556x; 1.1556x over previous
#include <cuda_runtime.h>
#include <cstdint>

#define Dd 512
#define Bb 32
#define Ss 2048

// -------- device scratch (static, no runtime allocation) --------
__device__ float g_wsc[Dd * Dd];            // tf32-rounded share_W
__device__ float g_wlc[8 * Dd * Dd];        // tf32-rounded langs_W
__device__ float g_w1c[8 * Dd * Dd];        // tf32-rounded gate_W1
__device__ float g_logit[Bb * Ss];          // gate logit accumulator

__device__ __forceinline__ uint32_t f2tf(float x) {
    uint32_t r;
    asm("cvt.rna.tf32.f32 %0, %1;" : "=r"(r) : "f"(x));
    return r;
}

__device__ __forceinline__ void mma8(float* d, const uint32_t* a, uint32_t b0, uint32_t b1) {
    asm volatile(
        "mma.sync.aligned.m16n8k8.row.col.f32.tf32.tf32.f32 "
        "{%0,%1,%2,%3}, {%4,%5,%6,%7}, {%8,%9}, {%0,%1,%2,%3};\n"
        : "+f"(d[0]), "+f"(d[1]), "+f"(d[2]), "+f"(d[3])
        : "r"(a[0]), "r"(a[1]), "r"(a[2]), "r"(a[3]), "r"(b0), "r"(b1));
}

__device__ __forceinline__ void cpa16(float* dst, const float* src) {
    uint32_t s = (uint32_t)__cvta_generic_to_shared(dst);
    asm volatile("cp.async.cg.shared.global [%0], [%1], 16;\n" :: "r"(s), "l"(src));
}
#define CP_COMMIT() asm volatile("cp.async.commit_group;\n" ::: "memory")
#define CP_WAIT1()  asm volatile("cp.async.wait_group 1;\n" ::: "memory")
#define CP_WAIT0()  asm volatile("cp.async.wait_group 0;\n" ::: "memory")

// common tile config
#define TM 128
#define TN 64
#define TK 32
#define ASTR 36          // 32 + 4 pad
#define BSTR 36
#define A_STAGE (TM * ASTR)   // 4608 floats
#define B_STAGE (TN * BSTR)   // 2304 floats

// ============================================================================
// convert_kernel: round weights to tf32 once (idempotent, runs every call)
// ============================================================================
__global__ void __launch_bounds__(256) convert_kernel(
    const float4* __restrict__ sW, const float4* __restrict__ lW,
    const float4* __restrict__ w1)
{
    const int stride = gridDim.x * blockDim.x;
    const int tid = blockIdx.x * blockDim.x + threadIdx.x;
    float4* dsc = (float4*)g_wsc;
    float4* dlc = (float4*)g_wlc;
    float4* d1c = (float4*)g_w1c;
    for (int i = tid; i < (Dd * Dd) / 4; i += stride) {
        float4 v = sW[i];
        v.x = __uint_as_float(f2tf(v.x)); v.y = __uint_as_float(f2tf(v.y));
        v.z = __uint_as_float(f2tf(v.z)); v.w = __uint_as_float(f2tf(v.w));
        dsc[i] = v;
    }
    for (int i = tid; i < (8 * Dd * Dd) / 4; i += stride) {
        float4 v = lW[i];
        v.x = __uint_as_float(f2tf(v.x)); v.y = __uint_as_float(f2tf(v.y));
        v.z = __uint_as_float(f2tf(v.z)); v.w = __uint_as_float(f2tf(v.w));
        dlc[i] = v;
    }
    for (int i = tid; i < (8 * Dd * Dd) / 4; i += stride) {
        float4 v = w1[i];
        v.x = __uint_as_float(f2tf(v.x)); v.y = __uint_as_float(f2tf(v.y));
        v.z = __uint_as_float(f2tf(v.z)); v.w = __uint_as_float(f2tf(v.w));
        d1c[i] = v;
    }
}

// ============================================================================
// init_kernel: g_logit[b,s] = b2[lang[b]]
// ============================================================================
__global__ void __launch_bounds__(256) init_kernel(
    const int* __restrict__ lang, const float* __restrict__ b2all)
{
    int idx = blockIdx.x * blockDim.x + threadIdx.x;
    if (idx < Bb * Ss) {
        int b = idx >> 11;            // S = 2048
        g_logit[idx] = b2all[lang[b]];
    }
}

// ============================================================================
// gate2_kernel: partial logit via GEMM old_x @ W1^T over a 128x64 e-tile.
// Epilogue: h = relu(acc + b1) + old_x ; partial = h . W2-chunk ; atomicAdd.
// 3-stage cp.async ring, ONE barrier per K-chunk.
// ============================================================================
__global__ void __launch_bounds__(256) gate2_kernel(
    const float* __restrict__ oldx, const int* __restrict__ lang,
    const float* __restrict__ b1all, const float* __restrict__ W2all)
{
    extern __shared__ float sm[];
    float* As = sm;                    // 3 * A_STAGE
    float* Bs = sm + 3 * A_STAGE;      // 3 * B_STAGE

    const int nt = blockIdx.x, mt = blockIdx.y, b = blockIdx.z;
    const int tid = threadIdx.x;
    const int lg = lang[b];
    const float* xb = oldx + ((size_t)b * Ss + (size_t)mt * TM) * Dd;
    const float* wb = g_w1c + (size_t)lg * Dd * Dd + (size_t)nt * TN * Dd;
    const float* b1 = b1all + (size_t)lg * Dd;
    const float* W2 = W2all + (size_t)lg * Dd;

    float acc[2][4][4];
    #pragma unroll
    for (int am = 0; am < 2; am++)
        #pragma unroll
        for (int an = 0; an < 4; an++)
            #pragma unroll
            for (int q = 0; q < 4; q++) acc[am][an][q] = 0.f;

    const int wid = tid >> 5, lane = tid & 31, g = lane >> 2, t4 = lane & 3;
    const int wm = (wid & 3) * 32, wn = (wid >> 2) * 32;  // 4m x 2n warps

    // prologue: prefetch K-chunks 0,1
    #pragma unroll
    for (int s = 0; s < 2; s++) {
        #pragma unroll
        for (int t = 0; t < 4; t++) {              // A: 128 rows * 8 f4
            int chunk = tid + t * 256;
            int row = chunk >> 3, c4 = (chunk & 7) * 4;
            cpa16(&As[s * A_STAGE + row * ASTR + c4], xb + row * Dd + s * TK + c4);
        }
        #pragma unroll
        for (int t = 0; t < 2; t++) {              // B: 64 rows * 8 f4
            int chunk = tid + t * 256;
            int row = chunk >> 3, c4 = (chunk & 7) * 4;
            cpa16(&Bs[s * B_STAGE + row * BSTR + c4], wb + row * Dd + s * TK + c4);
        }
        CP_COMMIT();
    }

    for (int kc = 0; kc < Dd / TK; kc++) {
        if (kc == Dd / TK - 1) { CP_WAIT0(); } else { CP_WAIT1(); }
        __syncthreads();
        if (kc + 2 < Dd / TK) {
            int s = (kc + 2) % 3, k0 = (kc + 2) * TK;
            #pragma unroll
            for (int t = 0; t < 4; t++) {
                int chunk = tid + t * 256;
                int row = chunk >> 3, c4 = (chunk & 7) * 4;
                cpa16(&As[s * A_STAGE + row * ASTR + c4], xb + row * Dd + k0 + c4);
            }
            #pragma unroll
            for (int t = 0; t < 2; t++) {
                int chunk = tid + t * 256;
                int row = chunk >> 3, c4 = (chunk & 7) * 4;
                cpa16(&Bs[s * B_STAGE + row * BSTR + c4], wb + row * Dd + k0 + c4);
            }
            CP_COMMIT();
        }
        const float* Ac = &As[(kc % 3) * A_STAGE];
        const float* Bc = &Bs[(kc % 3) * B_STAGE];
        #pragma unroll
        for (int ks = 0; ks < 4; ks++) {
            int k0 = ks * 8;
            uint32_t af[2][4];
            #pragma unroll
            for (int am = 0; am < 2; am++) {
                int r0 = wm + am * 16 + g;
                af[am][0] = f2tf(Ac[r0 * ASTR + k0 + t4]);
                af[am][1] = f2tf(Ac[(r0 + 8) * ASTR + k0 + t4]);
                af[am][2] = f2tf(Ac[r0 * ASTR + k0 + t4 + 4]);
                af[am][3] = f2tf(Ac[(r0 + 8) * ASTR + k0 + t4 + 4]);
            }
            #pragma unroll
            for (int an = 0; an < 4; an++) {
                int n = wn + an * 8 + g;
                uint32_t b0 = __float_as_uint(Bc[n * BSTR + k0 + t4]);
                uint32_t b1f = __float_as_uint(Bc[n * BSTR + k0 + t4 + 4]);
                #pragma unroll
                for (int am = 0; am < 2; am++)
                    mma8(acc[am][an], af[am], b0, b1f);
            }
        }
    }

    // epilogue: relu + bias + old_x, dot with W2 chunk, reduce, atomicAdd
    const int ebase = nt * TN + wn;
    #pragma unroll
    for (int am = 0; am < 2; am++) {
        #pragma unroll
        for (int i = 0; i < 2; i++) {
            int r = wm + am * 16 + g + i * 8;
            const float* oxr = xb + (size_t)r * Dd;
            float part = 0.f;
            #pragma unroll
            for (int an = 0; an < 4; an++) {
                int e = ebase + an * 8 + t4 * 2;
                float c0 = acc[am][an][2 * i], c1 = acc[am][an][2 * i + 1];
                float h0 = fmaxf(c0 + __ldg(&b1[e]), 0.f)     + __ldg(&oxr[e]);
                float h1 = fmaxf(c1 + __ldg(&b1[e + 1]), 0.f) + __ldg(&oxr[e + 1]);
                part += h0 * __ldg(&W2[e]) + h1 * __ldg(&W2[e + 1]);
            }
            // reduce over t4 (quad lanes)
            part += __shfl_xor_sync(0xffffffffu, part, 1);
            part += __shfl_xor_sync(0xffffffffu, part, 2);
            if (t4 == 0)
                atomicAdd(&g_logit[(size_t)b * Ss + (size_t)mt * TM + r], part);
        }
    }
}

// ============================================================================
// main2_kernel: out = (1-p) * x@share_W^T + p * x@langs_W[lang]^T
// p = sigmoid(g_logit). 3-stage ring, one barrier per K-chunk.
// ============================================================================
__global__ void __launch_bounds__(256) main2_kernel(
    const float* __restrict__ x, const int* __restrict__ lang,
    float* __restrict__ out)
{
    extern __shared__ float sm[];
    float* As = sm;                    // 3 * A_STAGE
    float* Bs = sm + 3 * A_STAGE;      // 3 stages * 2 tensors * B_STAGE

    const int nt = blockIdx.x, mt = blockIdx.y, b = blockIdx.z;
    const int tid = threadIdx.x;
    const int lg = lang[b];
    const float* xb = x + ((size_t)b * Ss + (size_t)mt * TM) * Dd;
    const float* ws = g_wsc + (size_t)nt * TN * Dd;
    const float* wl = g_wlc + (size_t)lg * Dd * Dd + (size_t)nt * TN * Dd;

    float accS[2][4][4], accL[2][4][4];
    #pragma unroll
    for (int am = 0; am < 2; am++)
        #pragma unroll
        for (int an = 0; an < 4; an++)
            #pragma unroll
            for (int q = 0; q < 4; q++) { accS[am][an][q] = 0.f; accL[am][an][q] = 0.f; }

    const int wid = tid >> 5, lane = tid & 31, g = lane >> 2, t4 = lane & 3;
    const int wm = (wid & 3) * 32, wn = (wid >> 2) * 32;

    // prologue
    #pragma unroll
    for (int s = 0; s < 2; s++) {
        #pragma unroll
        for (int t = 0; t < 4; t++) {
            int chunk = tid + t * 256;
            int row = chunk >> 3, c4 = (chunk & 7) * 4;
            cpa16(&As[s * A_STAGE + row * ASTR + c4], xb + row * Dd + s * TK + c4);
        }
        #pragma unroll
        for (int t = 0; t < 2; t++) {
            int chunk = tid + t * 256;
            int row = chunk >> 3, c4 = (chunk & 7) * 4;
            cpa16(&Bs[(s * 2 + 0) * B_STAGE + row * BSTR + c4], ws + row * Dd + s * TK + c4);
            cpa16(&Bs[(s * 2 + 1) * B_STAGE + row * BSTR + c4], wl + row * Dd + s * TK + c4);
        }
        CP_COMMIT();
    }

    for (int kc = 0; kc < Dd / TK; kc++) {
        if (kc == Dd / TK - 1) { CP_WAIT0(); } else { CP_WAIT1(); }
        __syncthreads();
        if (kc + 2 < Dd / TK) {
            int s = (kc + 2) % 3, k0 = (kc + 2) * TK;
            #pragma unroll
            for (int t = 0; t < 4; t++) {
                int chunk = tid + t * 256;
                int row = chunk >> 3, c4 = (chunk & 7) * 4;
                cpa16(&As[s * A_STAGE + row * ASTR + c4], xb + row * Dd + k0 + c4);
            }
            #pragma unroll
            for (int t = 0; t < 2; t++) {
                int chunk = tid + t * 256;
                int row = chunk >> 3, c4 = (chunk & 7) * 4;
                cpa16(&Bs[(s * 2 + 0) * B_STAGE + row * BSTR + c4], ws + row * Dd + k0 + c4);
                cpa16(&Bs[(s * 2 + 1) * B_STAGE + row * BSTR + c4], wl + row * Dd + k0 + c4);
            }
            CP_COMMIT();
        }
        const float* Ac  = &As[(kc % 3) * A_STAGE];
        const float* Bcs = &Bs[((kc % 3) * 2 + 0) * B_STAGE];
        const float* Bcl = &Bs[((kc % 3) * 2 + 1) * B_STAGE];
        #pragma unroll
        for (int ks = 0; ks < 4; ks++) {
            int k0 = ks * 8;
            uint32_t af[2][4];
            #pragma unroll
            for (int am = 0; am < 2; am++) {
                int r0 = wm + am * 16 + g;
                af[am][0] = f2tf(Ac[r0 * ASTR + k0 + t4]);
                af[am][1] = f2tf(Ac[(r0 + 8) * ASTR + k0 + t4]);
                af[am][2] = f2tf(Ac[r0 * ASTR + k0 + t4 + 4]);
                af[am][3] = f2tf(Ac[(r0 + 8) * ASTR + k0 + t4 + 4]);
            }
            #pragma unroll
            for (int an = 0; an < 4; an++) {
                int n = wn + an * 8 + g;
                uint32_t bs0 = __float_as_uint(Bcs[n * BSTR + k0 + t4]);
                uint32_t bs1 = __float_as_uint(Bcs[n * BSTR + k0 + t4 + 4]);
                uint32_t bl0 = __float_as_uint(Bcl[n * BSTR + k0 + t4]);
                uint32_t bl1 = __float_as_uint(Bcl[n * BSTR + k0 + t4 + 4]);
                #pragma unroll
                for (int am = 0; am < 2; am++) {
                    mma8(accS[am][an], af[am], bs0, bs1);
                    mma8(accL[am][an], af[am], bl0, bl1);
                }
            }
        }
    }

    // combine epilogue with sigmoid
    const size_t mbase = (size_t)b * Ss + (size_t)mt * TM;
    #pragma unroll
    for (int am = 0; am < 2; am++) {
        #pragma unroll
        for (int i = 0; i < 2; i++) {
            int r = wm + am * 16 + g + i * 8;
            float logit = g_logit[mbase + r];
            float p = 1.f / (1.f + expf(-logit));
            float q_ = 1.f - p;
            float* op = out + (mbase + r) * Dd + nt * TN + wn;
            #pragma unroll
            for (int an = 0; an < 4; an++) {
                float v0 = accS[am][an][2 * i]     * q_ + accL[am][an][2 * i]     * p;
                float v1 = accS[am][an][2 * i + 1] * q_ + accL[am][an][2 * i + 1] * p;
                *(float2*)(op + an * 8 + t4 * 2) = make_float2(v0, v1);
            }
        }
    }
}

// ============================================================================
extern "C" void kernel_launch(void* const* d_in, const int* in_sizes, int n_in,
                              void* d_out, int out_size) {
    const float* oldx   = (const float*)d_in[0];
    const float* x      = (const float*)d_in[1];
    const int*   lang   = (const int*)d_in[2];
    const float* shareW = (const float*)d_in[3];
    const float* langsW = (const float*)d_in[4];
    const float* gW1    = (const float*)d_in[5];
    const float* gb1    = (const float*)d_in[6];
    const float* gW2    = (const float*)d_in[7];
    const float* gb2    = (const float*)d_in[8];
    float* out = (float*)d_out;

    const int gsmem = (3 * A_STAGE + 3 * B_STAGE) * (int)sizeof(float);      // ~83 KB
    const int msmem = (3 * A_STAGE + 6 * B_STAGE) * (int)sizeof(float);      // ~110.6 KB
    cudaFuncSetAttribute(gate2_kernel, cudaFuncAttributeMaxDynamicSharedMemorySize, gsmem);
    cudaFuncSetAttribute(main2_kernel, cudaFuncAttributeMaxDynamicSharedMemorySize, msmem);

    convert_kernel<<<512, 256>>>((const float4*)shareW, (const float4*)langsW,
                                 (const float4*)gW1);
    init_kernel<<<(Bb * Ss + 255) / 256, 256>>>(lang, gb2);

    dim3 gg(Dd / TN, Ss / TM, Bb);
    gate2_kernel<<<gg, 256, gsmem>>>(oldx, lang, gb1, gW2);

    dim3 gm(Dd / TN, Ss / TM, Bb);
    main2_kernel<<<gm, 256, msmem>>>(x, lang, out);
}